// round 2
// baseline (speedup 1.0000x reference)
#include <cuda_runtime.h>
#include <math.h>

#define B 128
#define T 128
#define D 128
#define H 1024
#define TD (T*D)

#define KC 32        // k-chunk per smem stage
#define TB 64        // b-tile
#define TJ 8         // j-tile (hidden units per CTA)
#define LTHREADS 128
#define PTHREADS 128

// Persistent scratch (no allocation allowed; no cudaGetSymbolAddress either --
// kernels reference these symbols directly, selecting ping/pong by index arg).
// Hidden state and completed input are stored TRANSPOSED: h[j][b], comp[d][b]
// so GEMM A-tiles and epilogue I/O are coalesced.
__device__ float g_h[2][H * B];
__device__ float g_comp[D * B];

// ---------------------------------------------------------------------------
// init: zero h[0], comp[d][b] = x[b, 0, d]
// ---------------------------------------------------------------------------
__global__ void init_kernel(const float* __restrict__ x) {
    int i = blockIdx.x * blockDim.x + threadIdx.x;
    if (i < H * B) g_h[0][i] = 0.0f;
    if (i < D * B) {
        int d = i >> 7;      // i = d*128 + b
        int b = i & 127;
        g_comp[i] = x[b * TD + d];
    }
}

// ---------------------------------------------------------------------------
// One GEMM phase: acc[g][c] += sum_k A[k][b] * W[g*H + j, k]
// A is [K][B] row-major (stride B), W is [3H][K] row-major (stride K).
// Tile: rows k0..k0+KC-1 of A (cols b0..b0+63), 24 W rows (3 gates x 8 j).
// ---------------------------------------------------------------------------
__device__ __forceinline__ void accum_phase(
    const float* __restrict__ Amat, int K,
    const float* __restrict__ W,
    int j0, int b0, int bt, int jt, int tid,
    float* sA, float* sW, float (&acc)[3][4])
{
    for (int k0 = 0; k0 < K; k0 += KC) {
        __syncthreads();
        // stage A: KC rows x 64 cols (float4 tasks: KC*16)
        #pragma unroll
        for (int i = tid; i < KC * 16; i += LTHREADS) {
            int kr = i >> 4;
            int bq = i & 15;
            float4 v = *(const float4*)(Amat + (k0 + kr) * B + b0 + bq * 4);
            *(float4*)(sA + kr * 68 + bq * 4) = v;
        }
        // stage W: 24 rows x KC cols -> sW[k][slot], slot = g*8 + j
        #pragma unroll
        for (int i = tid; i < 24 * (KC / 4); i += LTHREADS) {
            int slot = i >> 3;          // 0..23   (KC/4 == 8)
            int q    = i & 7;
            int g  = slot >> 3;
            int jj = slot & 7;
            const float4 v = *(const float4*)(W + (size_t)(g * H + j0 + jj) * K + k0 + q * 4);
            sW[(q * 4 + 0) * 24 + slot] = v.x;
            sW[(q * 4 + 1) * 24 + slot] = v.y;
            sW[(q * 4 + 2) * 24 + slot] = v.z;
            sW[(q * 4 + 3) * 24 + slot] = v.w;
        }
        __syncthreads();
        #pragma unroll
        for (int k = 0; k < KC; k++) {
            float4 a = *(const float4*)(sA + k * 68 + bt * 4);
            float w0 = sW[k * 24 +      jt];
            float w1 = sW[k * 24 +  8 + jt];
            float w2 = sW[k * 24 + 16 + jt];
            acc[0][0] += a.x * w0; acc[0][1] += a.y * w0;
            acc[0][2] += a.z * w0; acc[0][3] += a.w * w0;
            acc[1][0] += a.x * w1; acc[1][1] += a.y * w1;
            acc[1][2] += a.z * w1; acc[1][3] += a.w * w1;
            acc[2][0] += a.x * w2; acc[2][1] += a.y * w2;
            acc[2][2] += a.z * w2; acc[2][3] += a.w * w2;
        }
    }
}

__device__ __forceinline__ float sigmoidf_(float v) {
    return 1.0f / (1.0f + expf(-v));
}

// ---------------------------------------------------------------------------
// Fused GRU layer: gi = A_in @ W_ih^T, gh = h_in @ W_hh^T, then pointwise
// update written to h_out. grid = (B/TB=2, H/TJ=128), 128 threads.
// use_comp != 0 -> layer 0 (input = g_comp, K_in = D); else input = hidden.
// cur selects hidden ping buffer; output goes to g_h[1-cur].
// ---------------------------------------------------------------------------
__global__ __launch_bounds__(LTHREADS) void gru_layer_kernel(
    int use_comp, int cur,
    const float* __restrict__ W_ih,              // [3H][K_in]
    const float* __restrict__ W_hh,              // [3H][H]
    const float* __restrict__ b_ih,
    const float* __restrict__ b_hh)
{
    __shared__ __align__(16) float sA[KC * 68];
    __shared__ __align__(16) float sW[KC * 24];

    const float* h_in  = g_h[cur];
    float*       h_out = g_h[1 - cur];
    const float* A_in  = use_comp ? g_comp : h_in;
    const int    K_in  = use_comp ? D : H;

    const int tid = threadIdx.x;
    const int bt  = tid & 15;      // 16 b-groups of 4
    const int jt  = tid >> 4;      // 8 j per CTA
    const int b0  = blockIdx.x * TB;
    const int j0  = blockIdx.y * TJ;

    float gi[3][4] = {{0.f,0.f,0.f,0.f},{0.f,0.f,0.f,0.f},{0.f,0.f,0.f,0.f}};
    float gh[3][4] = {{0.f,0.f,0.f,0.f},{0.f,0.f,0.f,0.f},{0.f,0.f,0.f,0.f}};

    accum_phase(A_in, K_in, W_ih, j0, b0, bt, jt, tid, sA, sW, gi);
    accum_phase(h_in, H,    W_hh, j0, b0, bt, jt, tid, sA, sW, gh);

    const int j = j0 + jt;
    const int b = b0 + bt * 4;
    const float bir = b_ih[j], biz = b_ih[H + j], bin_ = b_ih[2 * H + j];
    const float bhr = b_hh[j], bhz = b_hh[H + j], bhn = b_hh[2 * H + j];

    float4 hold = *(const float4*)(h_in + j * B + b);
    float ho[4];
    float hv[4] = {hold.x, hold.y, hold.z, hold.w};
    #pragma unroll
    for (int c = 0; c < 4; c++) {
        float r = sigmoidf_((gi[0][c] + bir) + (gh[0][c] + bhr));
        float z = sigmoidf_((gi[1][c] + biz) + (gh[1][c] + bhz));
        float n = tanhf((gi[2][c] + bin_) + r * (gh[2][c] + bhn));
        ho[c] = (1.0f - z) * n + z * hv[c];
    }
    float4 res = make_float4(ho[0], ho[1], ho[2], ho[3]);
    *(float4*)(h_out + j * B + b) = res;
}

// ---------------------------------------------------------------------------
// Projection + masking: imp = h @ Wp^T + bp ; comp = m*x_t + (1-m)*imp.
// Writes g_comp[d][b] (input to next step) and outputs for t < T-1.
// grid = (2, 32): b0 = bx*64, d0 = by*4. 128 threads, micro 2b x 1d.
// ---------------------------------------------------------------------------
__global__ __launch_bounds__(PTHREADS) void proj_kernel(
    int cur,
    const float* __restrict__ Wp,    // [D][H]
    const float* __restrict__ bp,
    const float* __restrict__ x,     // [B][T][D]
    const float* __restrict__ masks, // [B][T]
    int t,
    float* __restrict__ out_completed,  // [B][T-1][D]
    float* __restrict__ out_imputed)    // [B][T-1][D]
{
    __shared__ __align__(16) float sH[KC * 68];
    __shared__ float sWp[KC * 4];

    const float* h = g_h[cur];   // [H][B]

    const int tid = threadIdx.x;
    const int bt = tid & 31;    // 32 b-groups of 2
    const int dt = tid >> 5;    // 4 d per CTA
    const int b0 = blockIdx.x * 64;
    const int d0 = blockIdx.y * 4;

    float acc0 = 0.0f, acc1 = 0.0f;

    for (int k0 = 0; k0 < H; k0 += KC) {
        __syncthreads();
        #pragma unroll
        for (int i = tid; i < KC * 16; i += PTHREADS) {
            int kr = i >> 4;
            int bq = i & 15;
            float4 v = *(const float4*)(h + (k0 + kr) * B + b0 + bq * 4);
            *(float4*)(sH + kr * 68 + bq * 4) = v;
        }
        if (tid < 4 * (KC / 4)) {
            int slot = tid >> 3;      // 0..3
            int q    = tid & 7;
            const float4 v = *(const float4*)(Wp + (size_t)(d0 + slot) * H + k0 + q * 4);
            sWp[(q * 4 + 0) * 4 + slot] = v.x;
            sWp[(q * 4 + 1) * 4 + slot] = v.y;
            sWp[(q * 4 + 2) * 4 + slot] = v.z;
            sWp[(q * 4 + 3) * 4 + slot] = v.w;
        }
        __syncthreads();
        #pragma unroll
        for (int k = 0; k < KC; k++) {
            float2 a = *(const float2*)(sH + k * 68 + bt * 2);
            float w = sWp[k * 4 + dt];
            acc0 += a.x * w;
            acc1 += a.y * w;
        }
    }

    const int d = d0 + dt;
    const int b = b0 + bt * 2;
    const float bpv = bp[d];
    float imp0 = acc0 + bpv;
    float imp1 = acc1 + bpv;
    float m0 = masks[b * T + t];
    float m1 = masks[(b + 1) * T + t];
    float x0 = x[b * TD + t * D + d];
    float x1 = x[(b + 1) * TD + t * D + d];
    float c0 = m0 * x0 + (1.0f - m0) * imp0;
    float c1 = m1 * x1 + (1.0f - m1) * imp1;
    g_comp[d * B + b]     = c0;
    g_comp[d * B + b + 1] = c1;
    if (t < T - 1) {
        int base0 = b * (T - 1) * D + t * D + d;
        int base1 = (b + 1) * (T - 1) * D + t * D + d;
        out_completed[base0] = c0;
        out_completed[base1] = c1;
        out_imputed[base0] = imp0;
        out_imputed[base1] = imp1;
    }
}

// ---------------------------------------------------------------------------
// h_final: out[b*H + j] = h[j][b]
// ---------------------------------------------------------------------------
__global__ void copy_h_kernel(int cur, float* __restrict__ out) {
    int i = blockIdx.x * blockDim.x + threadIdx.x;
    if (i < H * B) {
        int b = i >> 10;
        int j = i & 1023;
        out[i] = g_h[cur][j * B + b];
    }
}

// ---------------------------------------------------------------------------
extern "C" void kernel_launch(void* const* d_in, const int* in_sizes, int n_in,
                              void* d_out, int out_size) {
    const float* x      = (const float*)d_in[0];
    const float* masks  = (const float*)d_in[1];
    const float* W_ih0  = (const float*)d_in[2];
    const float* W_hh0  = (const float*)d_in[3];
    const float* b_ih0  = (const float*)d_in[4];
    const float* b_hh0  = (const float*)d_in[5];
    const float* W_ih_r = (const float*)d_in[6];
    const float* W_hh_r = (const float*)d_in[7];
    const float* b_ih_r = (const float*)d_in[8];
    const float* b_hh_r = (const float*)d_in[9];
    const float* Wp     = (const float*)d_in[10];
    const float* bp     = (const float*)d_in[11];

    float* out = (float*)d_out;
    float* out_h         = out;
    float* out_completed = out + H * B;
    float* out_imputed   = out_completed + (size_t)B * (T - 1) * D;

    init_kernel<<<(H * B + 255) / 256, 256>>>(x);

    dim3 lgrid(B / TB, H / TJ);   // (2, 128)
    dim3 pgrid(2, 32);
    int cur = 0;
    for (int t = 0; t < T; t++) {
        // layer 0: input = completed from previous step (x[:,0] at t=0)
        gru_layer_kernel<<<lgrid, LTHREADS>>>(
            1, cur, W_ih0, W_hh0, b_ih0, b_hh0);
        cur ^= 1;
        // layers 1..L-1: input == hidden == h
        for (int l = 0; l < 2; l++) {
            const float* wih = W_ih_r + (size_t)l * 3 * H * H;
            const float* whh = W_hh_r + (size_t)l * 3 * H * H;
            gru_layer_kernel<<<lgrid, LTHREADS>>>(
                0, cur, wih, whh,
                b_ih_r + l * 3 * H, b_hh_r + l * 3 * H);
            cur ^= 1;
        }
        proj_kernel<<<pgrid, PTHREADS>>>(
            cur, Wp, bp, x, masks, t, out_completed, out_imputed);
    }
    copy_h_kernel<<<(H * B + 255) / 256, 256>>>(cur, out_h);
}

// round 3
// speedup vs baseline: 3.5839x; 3.5839x over previous
#include <cuda_runtime.h>
#include <cuda_bf16.h>
#include <math.h>

#define B 128
#define T 128
#define D 128
#define H 1024
#define TD (T*D)
#define JG 3072            // 3*H rows of gate outputs
#define SL (JG*B)          // slab elements

// ---------------------------------------------------------------------------
// Persistent scratch (static __device__; no allocation APIs anywhere).
// ---------------------------------------------------------------------------
// Split-bf16 weight cats: [jg][3K] = [hi | lo | hi]
__device__ __nv_bfloat16 g_w0cat[JG * 3 * D];        // W_ih0, K=128
__device__ __nv_bfloat16 g_wcat[5][JG * 3 * H];      // Whh0, Wih1, Whh1, Wih2, Whh2
// Split activations: [b][2K] = [hi | lo]
__device__ __nv_bfloat16 g_hsplit[B * 2 * H];
__device__ __nv_bfloat16 g_csplit[B * 2 * D];
// fp32 hidden (transposed [j][b]) ping-pong
__device__ float g_h32[2][H * B];
// GEMM partial-sum slabs: z = phase*3 + seg; [jg][b]
__device__ float g_slab[6 * SL];

// ---------------------------------------------------------------------------
// Weight split/cat conversion.  dstid = -1 -> g_w0cat, else g_wcat[dstid].
// out[j][k]      = bf16_hi(w)
// out[j][K+k]    = bf16_lo(w)
// out[j][2K+k]   = bf16_hi(w)   (duplicate; pairs with A_lo)
// ---------------------------------------------------------------------------
__global__ void convert_w_kernel(const float* __restrict__ W, int dstid, int K) {
    int i = blockIdx.x * blockDim.x + threadIdx.x;
    int n = JG * K;
    if (i >= n) return;
    int j = i / K;
    int k = i - j * K;
    float f = W[i];
    __nv_bfloat16 hi = __float2bfloat16_rn(f);
    __nv_bfloat16 lo = __float2bfloat16_rn(f - __bfloat162float(hi));
    __nv_bfloat16* out = (dstid < 0) ? g_w0cat : g_wcat[dstid];
    size_t base = (size_t)j * 3 * K;
    out[base + k]         = hi;
    out[base + K + k]     = lo;
    out[base + 2 * K + k] = hi;
}

// ---------------------------------------------------------------------------
// init: zero h32[0], zero hsplit, csplit = split(x[b,0,d])
// ---------------------------------------------------------------------------
__global__ void init_kernel(const float* __restrict__ x) {
    int i = blockIdx.x * blockDim.x + threadIdx.x;
    if (i < H * B) g_h32[0][i] = 0.0f;
    if (i < B * 2 * H) g_hsplit[i] = __float2bfloat16_rn(0.0f);
    if (i < B * D) {
        int d = i >> 7;
        int b = i & 127;
        float f = x[b * TD + d];
        __nv_bfloat16 hi = __float2bfloat16_rn(f);
        __nv_bfloat16 lo = __float2bfloat16_rn(f - __bfloat162float(hi));
        g_csplit[b * 2 * D + d]     = hi;
        g_csplit[b * 2 * D + D + d] = lo;
    }
}

// ---------------------------------------------------------------------------
// mma.sync helpers
// ---------------------------------------------------------------------------
__device__ __forceinline__ void mma16816(float c[4], const unsigned a[4], const unsigned b[2]) {
    asm volatile(
        "mma.sync.aligned.m16n8k16.row.col.f32.bf16.bf16.f32 "
        "{%0,%1,%2,%3}, {%4,%5,%6,%7}, {%8,%9}, {%0,%1,%2,%3};"
        : "+f"(c[0]), "+f"(c[1]), "+f"(c[2]), "+f"(c[3])
        : "r"(a[0]), "r"(a[1]), "r"(a[2]), "r"(a[3]), "r"(b[0]), "r"(b[1]));
}

__device__ __forceinline__ void ldsm4(unsigned r[4], unsigned addr) {
    asm volatile("ldmatrix.sync.aligned.m8n8.x4.shared.b16 {%0,%1,%2,%3}, [%4];"
                 : "=r"(r[0]), "=r"(r[1]), "=r"(r[2]), "=r"(r[3]) : "r"(addr));
}

__device__ __forceinline__ void cpasync16(unsigned dst, const void* src) {
    asm volatile("cp.async.cg.shared.global [%0], [%1], 16;" :: "r"(dst), "l"(src));
}
__device__ __forceinline__ void cpcommit() { asm volatile("cp.async.commit_group;"); }

// ---------------------------------------------------------------------------
// GEMM slab kernel.
// C_slab[z][jg][b] = sum_k Wseg[jg][k] * Aseg[b][k]
//   z = phase*3 + seg;  phase0 = gi (input side), phase1 = gh (hidden side)
//   seg0: A_hi x W_hi ; seg1: A_hi x W_lo ; seg2: A_lo x W_hi
// grid (48, 6), 256 threads. CTA tile 64 jg x 128 b, warp tile 32x32.
// K-chunks of 32, cp.async double-buffered, ldmatrix + mma m16n8k16 bf16.
// ---------------------------------------------------------------------------
#define SRW 40           // smem row stride in bf16 elems (conflict-free for ldmatrix)
#define WTILE_B (64 * SRW * 2)    // bytes per W buffer
#define BTILE_B (128 * SRW * 2)   // bytes per act buffer

__global__ __launch_bounds__(256) void gemm_kernel(int layer) {
    __shared__ __align__(16) __nv_bfloat16 sW[2][64 * SRW];
    __shared__ __align__(16) __nv_bfloat16 sB[2][128 * SRW];

    const int z     = blockIdx.y;
    const int phase = (z >= 3) ? 1 : 0;
    const int seg   = z - phase * 3;

    int K;
    const __nv_bfloat16* A;
    const __nv_bfloat16* W;
    if (phase) {
        A = g_hsplit; K = H;
        W = (layer == 0) ? g_wcat[0] : g_wcat[2 * layer];
    } else {
        if (layer == 0) { A = g_csplit; K = D; W = g_w0cat; }
        else            { A = g_hsplit; K = H; W = g_wcat[2 * layer - 1]; }
    }
    const int astride = 2 * K;
    const int wstride = 3 * K;
    const __nv_bfloat16* Ap = A + ((seg == 2) ? K : 0);
    const __nv_bfloat16* Wp = W + seg * K;
    float* slab = g_slab + (size_t)z * SL;

    const int j0   = blockIdx.x * 64;
    const int tid  = threadIdx.x;
    const int lane = tid & 31;
    const int wid  = tid >> 5;
    const int wj   = wid & 1;        // 2 jg-blocks of 32
    const int wb   = wid >> 1;       // 4 b-blocks of 32

    const unsigned sWu = (unsigned)__cvta_generic_to_shared(&sW[0][0]);
    const unsigned sBu = (unsigned)__cvta_generic_to_shared(&sB[0][0]);

    float acc[2][4][4];
    #pragma unroll
    for (int mi = 0; mi < 2; mi++)
        #pragma unroll
        for (int nb = 0; nb < 4; nb++)
            #pragma unroll
            for (int q = 0; q < 4; q++) acc[mi][nb][q] = 0.0f;

    const int S = K >> 5;   // 32-k chunks

    // stage loader: 768 x 16B tasks (W: 64 rows x 4, act: 128 rows x 4)
    auto stage = [&](int s, int buf) {
        #pragma unroll
        for (int p = 0; p < 3; p++) {
            int t = tid + (p << 8);
            if (t < 256) {
                int row = t >> 2, c = (t & 3) << 3;
                cpasync16(sWu + buf * WTILE_B + (row * SRW + c) * 2,
                          Wp + (size_t)(j0 + row) * wstride + s * 32 + c);
            } else {
                int t2 = t - 256;
                int row = t2 >> 2, c = (t2 & 3) << 3;
                cpasync16(sBu + buf * BTILE_B + (row * SRW + c) * 2,
                          Ap + (size_t)row * astride + s * 32 + c);
            }
        }
        cpcommit();
    };

    stage(0, 0);
    for (int s = 0; s < S; s++) {
        if (s + 1 < S) {
            stage(s + 1, (s + 1) & 1);
            asm volatile("cp.async.wait_group 1;");
        } else {
            asm volatile("cp.async.wait_group 0;");
        }
        __syncthreads();

        const int buf = s & 1;
        const unsigned swb = sWu + buf * WTILE_B;
        const unsigned sbb = sBu + buf * BTILE_B;

        #pragma unroll
        for (int kk = 0; kk < 32; kk += 16) {
            unsigned a0[4], a1[4], bfr[2][4];
            {   // A frags: rows = jg, ldmatrix.x4 on 16x16 tile
                int r = (lane & 15);
                int c = kk + ((lane & 16) ? 8 : 0);
                ldsm4(a0, swb + ((wj * 32 +      r) * SRW + c) * 2);
                ldsm4(a1, swb + ((wj * 32 + 16 + r) * SRW + c) * 2);
            }
            #pragma unroll
            for (int nbp = 0; nbp < 2; nbp++) {
                // B frags: two n8-blocks per ldmatrix.x4
                int m = lane >> 3;
                int n = wb * 32 + nbp * 16 + ((m & 2) ? 8 : 0) + (lane & 7);
                int c = kk + ((m & 1) ? 8 : 0);
                ldsm4(bfr[nbp], sbb + (n * SRW + c) * 2);
            }
            #pragma unroll
            for (int nbp = 0; nbp < 2; nbp++)
                #pragma unroll
                for (int hf = 0; hf < 2; hf++) {
                    int nb = nbp * 2 + hf;
                    mma16816(acc[0][nb], a0, &bfr[nbp][hf * 2]);
                    mma16816(acc[1][nb], a1, &bfr[nbp][hf * 2]);
                }
        }
        __syncthreads();
    }

    // write partials to slab
    #pragma unroll
    for (int mi = 0; mi < 2; mi++)
        #pragma unroll
        for (int nb = 0; nb < 4; nb++) {
            int jg = j0 + wj * 32 + mi * 16 + (lane >> 2);
            int b  = wb * 32 + nb * 8 + ((lane & 3) << 1);
            float2 v0 = make_float2(acc[mi][nb][0], acc[mi][nb][1]);
            float2 v1 = make_float2(acc[mi][nb][2], acc[mi][nb][3]);
            *(float2*)(slab + (size_t)jg * B + b)       = v0;
            *(float2*)(slab + (size_t)(jg + 8) * B + b) = v1;
        }
}

// ---------------------------------------------------------------------------
// Reduce slabs + GRU pointwise. Writes h32[1-cur] ([j][b]) and hsplit ([b][2H]).
// grid 512 x 256, thread i: b = i&127 (fastest), j = i>>7.
// ---------------------------------------------------------------------------
__global__ __launch_bounds__(256) void gru_epilogue_kernel(
    int cur, const float* __restrict__ b_ih, const float* __restrict__ b_hh)
{
    int i = blockIdx.x * blockDim.x + threadIdx.x;
    if (i >= H * B) return;
    int b = i & 127;
    int j = i >> 7;

    float gi[3], gh[3];
    #pragma unroll
    for (int g = 0; g < 3; g++) {
        int r = (g << 10) + j;
        size_t o = (size_t)r * B + b;
        gi[g] = g_slab[o] + g_slab[SL + o] + g_slab[2 * (size_t)SL + o] + b_ih[r];
        gh[g] = g_slab[3 * (size_t)SL + o] + g_slab[4 * (size_t)SL + o]
              + g_slab[5 * (size_t)SL + o] + b_hh[r];
    }
    float hp = g_h32[cur][j * B + b];
    float rg = 1.0f / (1.0f + expf(-(gi[0] + gh[0])));
    float zg = 1.0f / (1.0f + expf(-(gi[1] + gh[1])));
    float ng = tanhf(gi[2] + rg * gh[2]);
    float hn = (1.0f - zg) * ng + zg * hp;

    g_h32[1 - cur][j * B + b] = hn;
    __nv_bfloat16 hi = __float2bfloat16_rn(hn);
    __nv_bfloat16 lo = __float2bfloat16_rn(hn - __bfloat162float(hi));
    g_hsplit[b * 2 * H + j]     = hi;
    g_hsplit[b * 2 * H + H + j] = lo;
}

// ---------------------------------------------------------------------------
// Projection + masking (fp32 FFMA; small). Reads h32[cur] [j][b].
// Writes g_csplit (next-step layer-0 input) and outputs for t < T-1.
// ---------------------------------------------------------------------------
#define KC 32
__global__ __launch_bounds__(128) void proj_kernel(
    int cur,
    const float* __restrict__ Wp,    // [D][H]
    const float* __restrict__ bp,
    const float* __restrict__ x,     // [B][T][D]
    const float* __restrict__ masks, // [B][T]
    int t,
    float* __restrict__ out_completed,
    float* __restrict__ out_imputed)
{
    __shared__ __align__(16) float sH[KC * 68];
    __shared__ float sWp[KC * 4];

    const float* h = g_h32[cur];

    const int tid = threadIdx.x;
    const int bt = tid & 31;
    const int dt = tid >> 5;
    const int b0 = blockIdx.x * 64;
    const int d0 = blockIdx.y * 4;

    float acc0 = 0.0f, acc1 = 0.0f;

    for (int k0 = 0; k0 < H; k0 += KC) {
        __syncthreads();
        #pragma unroll
        for (int i = tid; i < KC * 16; i += 128) {
            int kr = i >> 4;
            int bq = i & 15;
            float4 v = *(const float4*)(h + (k0 + kr) * B + b0 + bq * 4);
            *(float4*)(sH + kr * 68 + bq * 4) = v;
        }
        if (tid < 32) {
            int slot = tid >> 3;
            int q    = tid & 7;
            const float4 v = *(const float4*)(Wp + (size_t)(d0 + slot) * H + k0 + q * 4);
            sWp[(q * 4 + 0) * 4 + slot] = v.x;
            sWp[(q * 4 + 1) * 4 + slot] = v.y;
            sWp[(q * 4 + 2) * 4 + slot] = v.z;
            sWp[(q * 4 + 3) * 4 + slot] = v.w;
        }
        __syncthreads();
        #pragma unroll
        for (int k = 0; k < KC; k++) {
            float2 a = *(const float2*)(sH + k * 68 + bt * 2);
            float w = sWp[k * 4 + dt];
            acc0 += a.x * w;
            acc1 += a.y * w;
        }
    }

    const int d = d0 + dt;
    const int b = b0 + bt * 2;
    const float bpv = bp[d];
    float imp0 = acc0 + bpv;
    float imp1 = acc1 + bpv;
    float m0 = masks[b * T + t];
    float m1 = masks[(b + 1) * T + t];
    float x0 = x[b * TD + t * D + d];
    float x1 = x[(b + 1) * TD + t * D + d];
    float c0 = m0 * x0 + (1.0f - m0) * imp0;
    float c1 = m1 * x1 + (1.0f - m1) * imp1;

    {   // split write for next-step layer-0 GEMM input
        __nv_bfloat16 h0c = __float2bfloat16_rn(c0);
        __nv_bfloat16 l0c = __float2bfloat16_rn(c0 - __bfloat162float(h0c));
        __nv_bfloat16 h1c = __float2bfloat16_rn(c1);
        __nv_bfloat16 l1c = __float2bfloat16_rn(c1 - __bfloat162float(h1c));
        g_csplit[b * 2 * D + d]           = h0c;
        g_csplit[b * 2 * D + D + d]       = l0c;
        g_csplit[(b + 1) * 2 * D + d]     = h1c;
        g_csplit[(b + 1) * 2 * D + D + d] = l1c;
    }
    if (t < T - 1) {
        int base0 = b * (T - 1) * D + t * D + d;
        int base1 = (b + 1) * (T - 1) * D + t * D + d;
        out_completed[base0] = c0;
        out_completed[base1] = c1;
        out_imputed[base0] = imp0;
        out_imputed[base1] = imp1;
    }
}

// ---------------------------------------------------------------------------
__global__ void copy_h_kernel(int cur, float* __restrict__ out) {
    int i = blockIdx.x * blockDim.x + threadIdx.x;
    if (i < H * B) {
        int b = i >> 10;
        int j = i & 1023;
        out[i] = g_h32[cur][j * B + b];
    }
}

// ---------------------------------------------------------------------------
extern "C" void kernel_launch(void* const* d_in, const int* in_sizes, int n_in,
                              void* d_out, int out_size) {
    const float* x      = (const float*)d_in[0];
    const float* masks  = (const float*)d_in[1];
    const float* W_ih0  = (const float*)d_in[2];
    const float* W_hh0  = (const float*)d_in[3];
    const float* b_ih0  = (const float*)d_in[4];
    const float* b_hh0  = (const float*)d_in[5];
    const float* W_ih_r = (const float*)d_in[6];
    const float* W_hh_r = (const float*)d_in[7];
    const float* b_ih_r = (const float*)d_in[8];
    const float* b_hh_r = (const float*)d_in[9];
    const float* Wp     = (const float*)d_in[10];
    const float* bp     = (const float*)d_in[11];

    float* out = (float*)d_out;
    float* out_h         = out;
    float* out_completed = out + H * B;
    float* out_imputed   = out_completed + (size_t)B * (T - 1) * D;

    // weight split/cat (cheap; once per launch)
    {
        int n0 = JG * D;
        convert_w_kernel<<<(n0 + 255) / 256, 256>>>(W_ih0, -1, D);
        int n1 = JG * H;
        convert_w_kernel<<<(n1 + 255) / 256, 256>>>(W_hh0, 0, H);
        convert_w_kernel<<<(n1 + 255) / 256, 256>>>(W_ih_r,               1, H);
        convert_w_kernel<<<(n1 + 255) / 256, 256>>>(W_hh_r,               2, H);
        convert_w_kernel<<<(n1 + 255) / 256, 256>>>(W_ih_r + (size_t)JG * H, 3, H);
        convert_w_kernel<<<(n1 + 255) / 256, 256>>>(W_hh_r + (size_t)JG * H, 4, H);
    }

    init_kernel<<<(B * 2 * H + 255) / 256, 256>>>(x);

    dim3 ggrid(48, 6);
    dim3 pgrid(2, 32);
    int cur = 0;
    for (int t = 0; t < T; t++) {
        // layer 0
        gemm_kernel<<<ggrid, 256>>>(0);
        gru_epilogue_kernel<<<512, 256>>>(cur, b_ih0, b_hh0);
        cur ^= 1;
        // layers 1, 2
        for (int l = 1; l < 3; l++) {
            gemm_kernel<<<ggrid, 256>>>(l);
            gru_epilogue_kernel<<<512, 256>>>(
                cur, b_ih_r + (size_t)(l - 1) * JG, b_hh_r + (size_t)(l - 1) * JG);
            cur ^= 1;
        }
        proj_kernel<<<pgrid, 128>>>(cur, Wp, bp, x, masks, t, out_completed, out_imputed);
    }
    copy_h_kernel<<<(H * B + 255) / 256, 256>>>(cur, out_h);
}